// round 1
// baseline (speedup 1.0000x reference)
#include <cuda_runtime.h>
#include <math.h>

#define E_TOT  800000
#define HALF_E 400000

// material id per element (0 -> (lam=1.0, mu=0.5), 1 -> (lam=2.0, mu=1.0))
__device__ unsigned char g_matid[E_TOT];

__global__ void mark_blocks_kernel(const int* __restrict__ b0,
                                   const int* __restrict__ b1) {
    int i = blockIdx.x * blockDim.x + threadIdx.x;
    if (i < HALF_E) {
        g_matid[b0[i]] = 0;
        g_matid[b1[i]] = 1;
    }
}

__global__ void __launch_bounds__(256)
hess_kernel(const float* __restrict__ U,        // [N,2]
            const float* __restrict__ state,    // [E,1,1]
            const int*   __restrict__ conns,    // [E,3]
            const float* __restrict__ sg,       // [E,1,3,2]
            const float* __restrict__ vols,     // [E,1]
            float*       __restrict__ out)      // [E,3,2,3,2]
{
    int e = blockIdx.x * blockDim.x + threadIdx.x;
    if (e >= E_TOT) return;

    // ---- streamed, coalesced element data ----
    int c0 = __ldg(&conns[3 * e + 0]);
    int c1 = __ldg(&conns[3 * e + 1]);
    int c2 = __ldg(&conns[3 * e + 2]);

    const float2* sgp = reinterpret_cast<const float2*>(sg + 6 * e);
    float2 g0 = sgp[0];
    float2 g1 = sgp[1];
    float2 g2 = sgp[2];

    float vol = __ldg(&vols[e]);
    float Q   = __ldg(&state[e]);
    int   m   = g_matid[e];

    float lam = m ? 2.0f : 1.0f;
    float mu  = m ? 1.0f : 0.5f;
    float mu_eff = mu * (1.0f + 0.01f * Q);

    // ---- gather nodal displacements (L2-resident table) ----
    const float2* U2 = reinterpret_cast<const float2*>(U);
    float2 u0 = __ldg(&U2[c0]);
    float2 u1 = __ldg(&U2[c1]);
    float2 u2 = __ldg(&U2[c2]);

    // gradU[c][d] = sum_n U[n][c] * g[n][d]
    float G00 = u0.x * g0.x + u1.x * g1.x + u2.x * g2.x;
    float G01 = u0.x * g0.y + u1.x * g1.y + u2.x * g2.y;
    float G10 = u0.y * g0.x + u1.y * g1.x + u2.y * g2.x;
    float G11 = u0.y * g0.y + u1.y * g1.y + u2.y * g2.y;

    float F00 = 1.0f + G00, F01 = G01;
    float F10 = G10,        F11 = 1.0f + G11;

    float J    = F00 * F11 - F01 * F10;
    float logJ = logf(J);
    float invJ = 1.0f / J;

    // Finv[l][i]
    float i00 =  F11 * invJ, i01 = -F01 * invJ;
    float i10 = -F10 * invJ, i11 =  F00 * invJ;

    float ga[3][2] = { {g0.x, g0.y}, {g1.x, g1.y}, {g2.x, g2.y} };

    // h[a][i] = sum_l g_a[l] * Finv[l][i]
    float h[3][2];
#pragma unroll
    for (int a = 0; a < 3; a++) {
        h[a][0] = ga[a][0] * i00 + ga[a][1] * i10;
        h[a][1] = ga[a][0] * i01 + ga[a][1] * i11;
    }

    float cgeo = mu_eff - lam * logJ;

    // H[a,i,b,j] = vol*( mu_eff*delta_ij*(g_a . g_b)
    //                    + cgeo * h_a[j]*h_b[i] + lam * h_a[i]*h_b[j] )
    float o[36];
#pragma unroll
    for (int a = 0; a < 3; a++) {
#pragma unroll
        for (int b = 0; b < 3; b++) {
            float gg = ga[a][0] * ga[b][0] + ga[a][1] * ga[b][1];
#pragma unroll
            for (int i = 0; i < 2; i++) {
#pragma unroll
                for (int j = 0; j < 2; j++) {
                    float v = cgeo * h[a][j] * h[b][i] + lam * h[a][i] * h[b][j];
                    if (i == j) v += mu_eff * gg;
                    o[((a * 2 + i) * 3 + b) * 2 + j] = v * vol;
                }
            }
        }
    }

    // 36 floats = 9 x float4, base offset 144B (16B aligned)
    float4* op = reinterpret_cast<float4*>(out + 36 * (size_t)e);
#pragma unroll
    for (int k = 0; k < 9; k++) {
        op[k] = make_float4(o[4 * k + 0], o[4 * k + 1], o[4 * k + 2], o[4 * k + 3]);
    }
}

extern "C" void kernel_launch(void* const* d_in, const int* in_sizes, int n_in,
                              void* d_out, int out_size) {
    // metadata order: U, coords, state, conns, shapes, shapeGrads, vols, blocks0, blocks1
    const float* U      = (const float*)d_in[0];
    // d_in[1] = coords  (unused by the energy)
    const float* state  = (const float*)d_in[2];
    const int*   conns  = (const int*)  d_in[3];
    // d_in[4] = shapes  (unused by the energy)
    const float* sg     = (const float*)d_in[5];
    const float* vols   = (const float*)d_in[6];
    const int*   b0     = (const int*)  d_in[7];
    const int*   b1     = (const int*)  d_in[8];
    float* out = (float*)d_out;

    {
        int threads = 256;
        int blocks = (HALF_E + threads - 1) / threads;
        mark_blocks_kernel<<<blocks, threads>>>(b0, b1);
    }
    {
        int threads = 256;
        int blocks = (E_TOT + threads - 1) / threads;
        hess_kernel<<<blocks, threads>>>(U, state, conns, sg, vols, out);
    }
}

// round 2
// speedup vs baseline: 1.5447x; 1.5447x over previous
#include <cuda_runtime.h>
#include <math.h>

#define E_TOT  800000
#define HALF_E 400000

// material id per element (0 -> (lam=1.0, mu=0.5), 1 -> (lam=2.0, mu=1.0))
__device__ unsigned char g_matid[E_TOT];

// coalesced zero of matid (800000 bytes = 50000 uint4)
__global__ void zero_matid_kernel() {
    int i = blockIdx.x * blockDim.x + threadIdx.x;
    if (i < E_TOT / 16) {
        reinterpret_cast<uint4*>(g_matid)[i] = make_uint4(0, 0, 0, 0);
    }
}

// scatter ones only for block1 (half the random traffic of marking both)
__global__ void mark_b1_kernel(const int* __restrict__ b1) {
    int i = blockIdx.x * blockDim.x + threadIdx.x;
    if (i < HALF_E) {
        g_matid[b1[i]] = 1;
    }
}

__global__ void __launch_bounds__(256)
hess_kernel(const float* __restrict__ U,        // [N,2]
            const float* __restrict__ state,    // [E,1,1]
            const int*   __restrict__ conns,    // [E,3]
            const float* __restrict__ sg,       // [E,1,3,2]
            const float* __restrict__ vols,     // [E,1]
            float*       __restrict__ out)      // [E,3,2,3,2]
{
    __shared__ float smem[256 * 37];   // 37-float stride: conflict-free staging

    const int tid = threadIdx.x;
    const int e   = blockIdx.x * 256 + tid;   // grid is exact: 3125*256 = 800000

    // ---- streamed, coalesced element data ----
    int c0 = __ldg(&conns[3 * e + 0]);
    int c1 = __ldg(&conns[3 * e + 1]);
    int c2 = __ldg(&conns[3 * e + 2]);

    const float2* sgp = reinterpret_cast<const float2*>(sg + 6 * e);
    float2 g0 = sgp[0];
    float2 g1 = sgp[1];
    float2 g2 = sgp[2];

    float vol = __ldg(&vols[e]);
    float Q   = __ldg(&state[e]);
    int   m   = g_matid[e];

    float lam = m ? 2.0f : 1.0f;
    float mu  = m ? 1.0f : 0.5f;
    float mu_eff = mu * (1.0f + 0.01f * Q);

    // ---- gather nodal displacements (L2-resident table) ----
    const float2* U2 = reinterpret_cast<const float2*>(U);
    float2 u0 = __ldg(&U2[c0]);
    float2 u1 = __ldg(&U2[c1]);
    float2 u2 = __ldg(&U2[c2]);

    // gradU[c][d] = sum_n U[n][c] * g[n][d]
    float G00 = u0.x * g0.x + u1.x * g1.x + u2.x * g2.x;
    float G01 = u0.x * g0.y + u1.x * g1.y + u2.x * g2.y;
    float G10 = u0.y * g0.x + u1.y * g1.x + u2.y * g2.x;
    float G11 = u0.y * g0.y + u1.y * g1.y + u2.y * g2.y;

    float F00 = 1.0f + G00, F01 = G01;
    float F10 = G10,        F11 = 1.0f + G11;

    float J    = F00 * F11 - F01 * F10;
    float logJ = __logf(J);
    float invJ = __frcp_rn(J);

    // Finv[l][i]
    float i00 =  F11 * invJ, i01 = -F01 * invJ;
    float i10 = -F10 * invJ, i11 =  F00 * invJ;

    float ga[3][2] = { {g0.x, g0.y}, {g1.x, g1.y}, {g2.x, g2.y} };

    // h[a][i] = sum_l g_a[l] * Finv[l][i]
    float h[3][2];
#pragma unroll
    for (int a = 0; a < 3; a++) {
        h[a][0] = ga[a][0] * i00 + ga[a][1] * i10;
        h[a][1] = ga[a][0] * i01 + ga[a][1] * i11;
    }

    float cgeo = mu_eff - lam * logJ;

    // H[a,i,b,j] = vol*( mu_eff*delta_ij*(g_a . g_b)
    //                    + cgeo * h_a[j]*h_b[i] + lam * h_a[i]*h_b[j] )
    float* row = smem + tid * 37;
#pragma unroll
    for (int a = 0; a < 3; a++) {
#pragma unroll
        for (int b = 0; b < 3; b++) {
            float gg = ga[a][0] * ga[b][0] + ga[a][1] * ga[b][1];
#pragma unroll
            for (int i = 0; i < 2; i++) {
#pragma unroll
                for (int j = 0; j < 2; j++) {
                    float v = cgeo * h[a][j] * h[b][i] + lam * h[a][i] * h[b][j];
                    if (i == j) v += mu_eff * gg;
                    row[((a * 2 + i) * 3 + b) * 2 + j] = v * vol;
                }
            }
        }
    }

    __syncthreads();

    // coalesced copy-out: 256*36 floats per block, 36 iterations of
    // perfectly-coalesced 128B-per-warp STG.32
    float* oblk = out + (size_t)blockIdx.x * (256 * 36);
#pragma unroll
    for (int it = 0; it < 36; it++) {
        int j = it * 256 + tid;
        int el = j / 36;
        int k  = j - el * 36;
        oblk[j] = smem[el * 37 + k];
    }
}

extern "C" void kernel_launch(void* const* d_in, const int* in_sizes, int n_in,
                              void* d_out, int out_size) {
    // metadata order: U, coords, state, conns, shapes, shapeGrads, vols, blocks0, blocks1
    const float* U      = (const float*)d_in[0];
    // d_in[1] = coords  (unused by the energy)
    const float* state  = (const float*)d_in[2];
    const int*   conns  = (const int*)  d_in[3];
    // d_in[4] = shapes  (unused by the energy)
    const float* sg     = (const float*)d_in[5];
    const float* vols   = (const float*)d_in[6];
    // d_in[7] = blocks0 (implied by zeroing)
    const int*   b1     = (const int*)  d_in[8];
    float* out = (float*)d_out;

    {
        int n = E_TOT / 16;
        zero_matid_kernel<<<(n + 255) / 256, 256>>>();
    }
    {
        mark_b1_kernel<<<(HALF_E + 255) / 256, 256>>>(b1);
    }
    {
        hess_kernel<<<E_TOT / 256, 256>>>(U, state, conns, sg, vols, out);
    }
}

// round 3
// speedup vs baseline: 1.8241x; 1.1809x over previous
#include <cuda_runtime.h>
#include <math.h>

#define E_TOT  800000
#define HALF_E 400000
#define TPB    256

// material id per element (0 -> (lam=1.0, mu=0.5), 1 -> (lam=2.0, mu=1.0))
__device__ unsigned char g_matid[E_TOT];

// scatter ones only for block1 (zeroing handled by cudaMemsetAsync)
__global__ void mark_b1_kernel(const int* __restrict__ b1) {
    int i = blockIdx.x * blockDim.x + threadIdx.x;
    if (i < HALF_E) {
        g_matid[b1[i]] = 1;
    }
}

__global__ void __launch_bounds__(TPB)
hess_kernel(const float* __restrict__ U,        // [N,2]
            const float* __restrict__ state,    // [E,1,1]
            const int*   __restrict__ conns,    // [E,3]
            const float* __restrict__ sg,       // [E,1,3,2]
            const float* __restrict__ vols,     // [E,1]
            float*       __restrict__ out)      // [E,3,2,3,2]
{
    // One buffer, reused: first for staged inputs, then for staged outputs.
    // Output staging: element-contiguous, stride 36 floats (144B, 16B aligned).
    __shared__ float smem[TPB * 36];

    const int tid = threadIdx.x;
    const int blk = blockIdx.x;
    const int e   = blk * TPB + tid;          // grid exact: 3125*256 = 800000

    // ---- cooperative coalesced staging of sg [6 floats/elem] and conns [3 ints/elem]
    {
        const float* sgb = sg + (size_t)blk * (TPB * 6);
#pragma unroll
        for (int it = 0; it < 6; it++)
            smem[it * TPB + tid] = sgb[it * TPB + tid];
        int* conn_s = reinterpret_cast<int*>(smem + 6 * TPB);
        const int* cb = conns + (size_t)blk * (TPB * 3);
#pragma unroll
        for (int it = 0; it < 3; it++)
            conn_s[it * TPB + tid] = cb[it * TPB + tid];
    }
    __syncthreads();

    // per-thread reads from smem (conflict-free patterns)
    float2 g0, g1, g2;
    {
        const float2* p = reinterpret_cast<const float2*>(smem + tid * 6);
        g0 = p[0]; g1 = p[1]; g2 = p[2];
    }
    int c0, c1, c2;
    {
        const int* conn_s = reinterpret_cast<const int*>(smem + 6 * TPB);
        c0 = conn_s[tid * 3 + 0];
        c1 = conn_s[tid * 3 + 1];
        c2 = conn_s[tid * 3 + 2];
    }

    float vol = __ldg(&vols[e]);
    float Q   = __ldg(&state[e]);
    int   m   = g_matid[e];

    float lam = m ? 2.0f : 1.0f;
    float mu  = m ? 1.0f : 0.5f;
    float mu_eff = mu * (1.0f + 0.01f * Q);

    // ---- gather nodal displacements (L2-resident table) ----
    const float2* U2 = reinterpret_cast<const float2*>(U);
    float2 u0 = __ldg(&U2[c0]);
    float2 u1 = __ldg(&U2[c1]);
    float2 u2 = __ldg(&U2[c2]);

    __syncthreads();   // everyone done reading staged inputs; buffer reusable

    // gradU[c][d] = sum_n U[n][c] * g[n][d]
    float G00 = u0.x * g0.x + u1.x * g1.x + u2.x * g2.x;
    float G01 = u0.x * g0.y + u1.x * g1.y + u2.x * g2.y;
    float G10 = u0.y * g0.x + u1.y * g1.x + u2.y * g2.x;
    float G11 = u0.y * g0.y + u1.y * g1.y + u2.y * g2.y;

    float F00 = 1.0f + G00, F01 = G01;
    float F10 = G10,        F11 = 1.0f + G11;

    float J    = F00 * F11 - F01 * F10;
    float logJ = __logf(J);
    float invJ = __frcp_rn(J);

    // Finv[l][i]
    float i00 =  F11 * invJ, i01 = -F01 * invJ;
    float i10 = -F10 * invJ, i11 =  F00 * invJ;

    float ga[3][2] = { {g0.x, g0.y}, {g1.x, g1.y}, {g2.x, g2.y} };

    // h[a][i] = sum_l g_a[l] * Finv[l][i]
    float h[3][2];
#pragma unroll
    for (int a = 0; a < 3; a++) {
        h[a][0] = ga[a][0] * i00 + ga[a][1] * i10;
        h[a][1] = ga[a][0] * i01 + ga[a][1] * i11;
    }

    float cgeo = mu_eff - lam * logJ;

    // H[a,i,b,j] = vol*( mu_eff*delta_ij*(g_a . g_b)
    //                    + cgeo * h_a[j]*h_b[i] + lam * h_a[i]*h_b[j] )
    // stage element-contiguous (stride 36 floats), 9x STS.128 conflict-free
    float o[36];
#pragma unroll
    for (int a = 0; a < 3; a++) {
#pragma unroll
        for (int b = 0; b < 3; b++) {
            float gg = ga[a][0] * ga[b][0] + ga[a][1] * ga[b][1];
#pragma unroll
            for (int i = 0; i < 2; i++) {
#pragma unroll
                for (int j = 0; j < 2; j++) {
                    float v = cgeo * h[a][j] * h[b][i] + lam * h[a][i] * h[b][j];
                    if (i == j) v += mu_eff * gg;
                    o[((a * 2 + i) * 3 + b) * 2 + j] = v * vol;
                }
            }
        }
    }

    {
        float4* row = reinterpret_cast<float4*>(smem + tid * 36);
#pragma unroll
        for (int k = 0; k < 9; k++)
            row[k] = make_float4(o[4 * k + 0], o[4 * k + 1], o[4 * k + 2], o[4 * k + 3]);
    }

    __syncthreads();

    // linear copy-out: 2304 float4 per block, LDS.128 + STG.128, fully coalesced
    {
        const float4* s4 = reinterpret_cast<const float4*>(smem);
        float4* o4 = reinterpret_cast<float4*>(out) + (size_t)blk * (TPB * 9);
#pragma unroll
        for (int it = 0; it < 9; it++)
            o4[it * TPB + tid] = s4[it * TPB + tid];
    }
}

extern "C" void kernel_launch(void* const* d_in, const int* in_sizes, int n_in,
                              void* d_out, int out_size) {
    // metadata order: U, coords, state, conns, shapes, shapeGrads, vols, blocks0, blocks1
    const float* U      = (const float*)d_in[0];
    // d_in[1] = coords  (unused by the energy)
    const float* state  = (const float*)d_in[2];
    const int*   conns  = (const int*)  d_in[3];
    // d_in[4] = shapes  (unused by the energy)
    const float* sg     = (const float*)d_in[5];
    const float* vols   = (const float*)d_in[6];
    // d_in[7] = blocks0 (implied 0 by the memset)
    const int*   b1     = (const int*)  d_in[8];
    float* out = (float*)d_out;

    void* matid_ptr = nullptr;
    cudaGetSymbolAddress(&matid_ptr, g_matid);
    cudaMemsetAsync(matid_ptr, 0, E_TOT);

    mark_b1_kernel<<<(HALF_E + TPB - 1) / TPB, TPB>>>(b1);

    hess_kernel<<<E_TOT / TPB, TPB>>>(U, state, conns, sg, vols, out);
}